// round 14
// baseline (speedup 1.0000x reference)
#include <cuda_runtime.h>
#include <cuda_bf16.h>
#include <cstdint>

// SeparationLoss: mean over B of sum_{i!=j} max(0, thr2 - ||kp_i - kp_j||^2)
// Input: batched_kps [B, 17, 3] f32 (B = 131072). Output: scalar f32.
//
// R14: f32x2 attempt #3 with both prior failure modes removed.
//   - 2 rows/thread packed in u64 lanes; fma.rn.f32x2 cuts fma-pipe cycles
//     per pair from 20 to 12 (the plateau-binding quantity).
//   - R2's reg blowup fixed by two-pass joint tiling (0-8 resident + stream,
//     then 9-16 resident).
//   - R7's alu MOV bloat fixed: pack ONLY at load (LDS pairs), unpack-only on
//     results (free aliasing), 4 SCALAR accumulators (no per-pair pack2).
// 256 rows/block, one bulk copy, grid 512 (one wave at 4 blocks/SM).

#define J 17
#define ROW_F 51                    // 17*3 floats per row
#define TILE_ROWS 256
#define THREADS 128                 // thread t -> local rows 2t, 2t+1
#define TILE_BYTES (TILE_ROWS * ROW_F * 4)    // 52224
#define NBLOCKS_MAX 8192

__device__ __align__(16) float g_partials[NBLOCKS_MAX];
__device__ unsigned int g_done_count;   // zero-init; inc wraps -> self-resets per run

typedef unsigned long long u64;

__device__ __forceinline__ uint32_t smem_u32(const void* p) {
    uint32_t a;
    asm("{ .reg .u64 t; cvta.to.shared.u64 t, %1; cvt.u32.u64 %0, t; }"
        : "=r"(a) : "l"(p));
    return a;
}
__device__ __forceinline__ u64 pack2(float lo, float hi) {
    u64 r; asm("mov.b64 %0, {%1, %2};" : "=l"(r) : "f"(lo), "f"(hi)); return r;
}
__device__ __forceinline__ void unpack2(u64 v, float& lo, float& hi) {
    asm("mov.b64 {%0, %1}, %2;" : "=f"(lo), "=f"(hi) : "l"(v));
}
__device__ __forceinline__ u64 fma2(u64 a, u64 b, u64 c) {
    u64 d; asm("fma.rn.f32x2 %0, %1, %2, %3;" : "=l"(d) : "l"(a), "l"(b), "l"(c));
    return d;
}
__device__ __forceinline__ u64 add2(u64 a, u64 b) {
    u64 d; asm("add.rn.f32x2 %0, %1, %2;" : "=l"(d) : "l"(a), "l"(b));
    return d;
}
__device__ __forceinline__ u64 mul2(u64 a, u64 b) {
    u64 d; asm("mul.rn.f32x2 %0, %1, %2;" : "=l"(d) : "l"(a), "l"(b));
    return d;
}

__device__ __forceinline__ void mbar_wait0(uint32_t mb) {
    uint32_t done;
    asm volatile(
        "{\n\t.reg .pred p;\n\t"
        "mbarrier.try_wait.parity.acquire.cta.shared::cta.b64 p, [%1], 0;\n\t"
        "selp.b32 %0, 1, 0, p;\n\t}"
        : "=r"(done) : "r"(mb) : "memory");
    if (!done) {
        asm volatile(
            "{\n\t.reg .pred P1;\n\t"
            "W_%=:\n\t"
            "mbarrier.try_wait.parity.acquire.cta.shared::cta.b64 P1, [%0], 0, 0x989680;\n\t"
            "@P1 bra.uni D_%=;\n\t"
            "bra.uni W_%=;\n\t"
            "D_%=:\n\t}"
            :: "r"(mb) : "memory");
    }
}

// one pair over 2 rows: 1 add2 + 3 fma2 (fma pipe) + 2 FMNMX (alu) + 2 FADD.
// NO pack2 here -- results are unpack-only (register aliasing).
#define PAIR2(AX, AY, AZ, GI, BX, BY, BZ, GJ)                          \
    {                                                                  \
        u64 w = add2((GI), (GJ));                                      \
        u64 d = fma2((AZ), (BZ), fma2((AY), (BY), fma2((AX), (BX), w)));\
        float dl, dh; unpack2(d, dl, dh);                              \
        float hl = fmaxf(dl, 0.0f), hh = fmaxf(dh, 0.0f);              \
        if (k & 1) { aL1 += hl; aH1 += hh; }                           \
        else       { aL0 += hl; aH0 += hh; }                           \
        k++;                                                           \
    }

// packed g = 0.25*thr2 - 0.5*||p||^2 for both rows
#define G2(X, Y, Z) fma2(fma2((Z), (Z), fma2((Y), (Y), mul2((X), (X)))), nhalf2, thrq2)

__global__ __launch_bounds__(THREADS, 4)   // 128-reg cap; ~90 demand
void sep_loss_fused(const float* __restrict__ kps, int B, int grid,
                    float invB, float* __restrict__ out) {
    __shared__ __align__(16) float s[TILE_ROWS * ROW_F];   // 52224 B
    __shared__ __align__(8)  unsigned long long mbar;
    __shared__ float wsum[THREADS / 32];
    __shared__ bool  isLast;

    const int tid = threadIdx.x;
    const int rowBase = blockIdx.x * TILE_ROWS;
    const int rowsHere = min(TILE_ROWS, B - rowBase);
    const uint32_t mb = smem_u32(&mbar);

    if (rowsHere == TILE_ROWS) {
        if (tid == 0) {
            asm volatile("mbarrier.init.shared.b64 [%0], 1;" :: "r"(mb) : "memory");
        }
        __syncthreads();
        if (tid == 0) {
            asm volatile("mbarrier.arrive.expect_tx.shared.b64 _, [%0], %1;"
                         :: "r"(mb), "r"((uint32_t)TILE_BYTES) : "memory");
            asm volatile(
                "cp.async.bulk.shared::cta.global.mbarrier::complete_tx::bytes "
                "[%0], [%1], %2, [%3];"
                :: "r"(smem_u32(s)), "l"(kps + (size_t)rowBase * ROW_F),
                   "r"((uint32_t)TILE_BYTES), "r"(mb)
                : "memory");
        }
        mbar_wait0(mb);
    } else {
        const float* src = kps + (size_t)rowBase * ROW_F;
        for (int i = tid; i < rowsHere * ROW_F; i += THREADS) s[i] = src[i];
        __syncthreads();
    }

    const int r0 = 2 * tid, r1 = 2 * tid + 1;
    const bool v0 = r0 < rowsHere, v1 = r1 < rowsHere;
    const float* __restrict__ rp0 = s + (v0 ? r0 : 0) * ROW_F;
    const float* __restrict__ rp1 = s + (v1 ? r1 : 0) * ROW_F;

    const u64 nhalf2 = pack2(-0.5f, -0.5f);
    const u64 thrq2  = pack2(0.0025f, 0.0025f);    // 0.25 * thr2
    float aL0 = 0.0f, aL1 = 0.0f, aH0 = 0.0f, aH1 = 0.0f;
    int k = 0;

    // ================= PASS 1: joints 0..8 resident (packed) =================
    {
        u64 q[27];
        u64 g2[9];
        #pragma unroll
        for (int c = 0; c < 27; c++) q[c] = pack2(rp0[c], rp1[c]);
        #pragma unroll
        for (int i = 0; i < 9; i++)
            g2[i] = G2(q[3*i], q[3*i+1], q[3*i+2]);

        // intra pairs among joints 0..8: 36
        #pragma unroll
        for (int i = 0; i < 9; i++)
            #pragma unroll
            for (int j = i + 1; j < 9; j++)
                PAIR2(q[3*i], q[3*i+1], q[3*i+2], g2[i],
                      q[3*j], q[3*j+1], q[3*j+2], g2[j]);

        // cross pairs: stream joints 9..16 (72 pairs)
        #pragma unroll
        for (int jj = 0; jj < 8; jj++) {
            u64 sx = pack2(rp0[27 + 3*jj    ], rp1[27 + 3*jj    ]);
            u64 sy = pack2(rp0[27 + 3*jj + 1], rp1[27 + 3*jj + 1]);
            u64 sz = pack2(rp0[27 + 3*jj + 2], rp1[27 + 3*jj + 2]);
            u64 sg = G2(sx, sy, sz);
            #pragma unroll
            for (int i = 0; i < 9; i++)
                PAIR2(q[3*i], q[3*i+1], q[3*i+2], g2[i], sx, sy, sz, sg);
        }
    }

    // ================= PASS 2: joints 9..16 resident (packed) =================
    {
        u64 q[24];
        u64 g2[8];
        #pragma unroll
        for (int c = 0; c < 24; c++) q[c] = pack2(rp0[27 + c], rp1[27 + c]);
        #pragma unroll
        for (int i = 0; i < 8; i++)
            g2[i] = G2(q[3*i], q[3*i+1], q[3*i+2]);

        // intra pairs among joints 9..16: 28
        #pragma unroll
        for (int i = 0; i < 8; i++)
            #pragma unroll
            for (int j = i + 1; j < 8; j++)
                PAIR2(q[3*i], q[3*i+1], q[3*i+2], g2[i],
                      q[3*j], q[3*j+1], q[3*j+2], g2[j]);
    }

    // hinge = 2*max(0,d); ordered pairs double again -> x4
    float accLo = v0 ? (aL0 + aL1) : 0.0f;
    float accHi = v1 ? (aH0 + aH1) : 0.0f;
    float acc = (accLo + accHi) * 4.0f;

    // ---- deterministic block reduction (4 warps) ----
    #pragma unroll
    for (int off = 16; off > 0; off >>= 1)
        acc += __shfl_down_sync(0xFFFFFFFFu, acc, off);
    if ((tid & 31) == 0) wsum[tid >> 5] = acc;
    __syncthreads();

    if (tid == 0) {
        g_partials[blockIdx.x] = (wsum[0] + wsum[1]) + (wsum[2] + wsum[3]);
        // release-inc orders the store; wraps to 0 at grid-1 (replay-safe)
        unsigned int c;
        asm volatile("atom.acq_rel.gpu.global.inc.u32 %0, [%1], %2;"
                     : "=r"(c)
                     : "l"(&g_done_count), "r"((unsigned int)(grid - 1))
                     : "memory");
        isLast = (c == (unsigned int)(grid - 1));
    }
    __syncthreads();

    // ---- last block: 512 partials = 1 float4 per thread ----
    if (isLast) {
        float v = 0.0f;
        const int nvec = grid >> 2;               // 128 for grid=512
        const float4* gp = reinterpret_cast<const float4*>(g_partials);
        for (int i = tid; i < nvec; i += THREADS) {
            float4 f = gp[i];
            v += (f.x + f.y) + (f.z + f.w);
        }
        for (int i = (nvec << 2) + tid; i < grid; i += THREADS)
            v += g_partials[i];
        #pragma unroll
        for (int off = 16; off > 0; off >>= 1)
            v += __shfl_down_sync(0xFFFFFFFFu, v, off);
        if ((tid & 31) == 0) wsum[tid >> 5] = v;
        __syncthreads();
        if (tid == 0)
            out[0] = ((wsum[0] + wsum[1]) + (wsum[2] + wsum[3])) * invB;
    }
}

extern "C" void kernel_launch(void* const* d_in, const int* in_sizes, int n_in,
                              void* d_out, int out_size) {
    const float* kps = (const float*)d_in[0];
    const int B = in_sizes[0] / ROW_F;
    const int grid = (B + TILE_ROWS - 1) / TILE_ROWS;   // 512 for B=131072

    sep_loss_fused<<<grid, THREADS>>>(kps, B, grid, 1.0f / (float)B,
                                      (float*)d_out);
}

// round 15
// speedup vs baseline: 1.5038x; 1.5038x over previous
#include <cuda_runtime.h>
#include <cuda_bf16.h>
#include <cstdint>

// SeparationLoss: mean over B of sum_{i!=j} max(0, thr2 - ||kp_i - kp_j||^2)
// Input: batched_kps [B, 17, 3] f32 (B = 131072). Output: scalar f32.
//
// R15: pair-parity split. Each row is processed by TWO threads (in different
// warps, warp-uniform role): template<HALF> constant-folds the parity test so
// each thread executes exactly 68 of the 136 pairs with ZERO added ops.
// Per-warp critical path halves at unchanged register pressure (~80).
// Gram-identity core, bulk-copy staging, fused last-block-done reduction.

#define J 17
#define ROW_F 51                    // 17*3 floats per row
#define TILE_ROWS 64
#define THREADS 128                 // warps 0-1: HALF=0, warps 2-3: HALF=1
#define TILE_BYTES (TILE_ROWS * ROW_F * 4)    // 13056
#define NBLOCKS_MAX 8192

__device__ __align__(16) float g_partials[NBLOCKS_MAX];
__device__ unsigned int g_done_count;   // zero-init; inc wraps -> self-resets per run

__device__ __forceinline__ uint32_t smem_u32(const void* p) {
    uint32_t a;
    asm("{ .reg .u64 t; cvta.to.shared.u64 t, %1; cvt.u32.u64 %0, t; }"
        : "=r"(a) : "l"(p));
    return a;
}

__device__ __forceinline__ void mbar_wait0(uint32_t mb) {
    uint32_t done;
    asm volatile(
        "{\n\t.reg .pred p;\n\t"
        "mbarrier.try_wait.parity.acquire.cta.shared::cta.b64 p, [%1], 0;\n\t"
        "selp.b32 %0, 1, 0, p;\n\t}"
        : "=r"(done) : "r"(mb) : "memory");
    if (!done) {
        asm volatile(
            "{\n\t.reg .pred P1;\n\t"
            "W_%=:\n\t"
            "mbarrier.try_wait.parity.acquire.cta.shared::cta.b64 P1, [%0], 0, 0x989680;\n\t"
            "@P1 bra.uni D_%=;\n\t"
            "bra.uni W_%=;\n\t"
            "D_%=:\n\t}"
            :: "r"(mb) : "memory");
    }
}

// Sum of max(0, g_i+g_j+<p_i,p_j>) over the 68 pairs whose enumeration index
// has parity HALF. Fully unrolled; k folds at compile time.
template<int HALF>
__device__ __forceinline__ float row_pairs_half(const float* __restrict__ rp) {
    float p[ROW_F];
    float g[J];
    #pragma unroll
    for (int c = 0; c < ROW_F; c++) p[c] = rp[c];
    #pragma unroll
    for (int i = 0; i < J; i++) {
        float x = p[3*i], y = p[3*i+1], z = p[3*i+2];
        float r = fmaf(z, z, fmaf(y, y, x * x));
        g[i] = fmaf(r, -0.5f, 0.0025f);      // 0.25*thr2; FFMA-imm
    }
    float a0 = 0.0f, a1 = 0.0f;
    int k = 0;
    #pragma unroll
    for (int i = 0; i < J; i++) {
        #pragma unroll
        for (int j = i + 1; j < J; j++) {
            if ((k & 1) == HALF) {           // folds: exactly 68 pairs emitted
                float w = g[i] + g[j];
                float d = fmaf(p[3*i+2], p[3*j+2],
                          fmaf(p[3*i+1], p[3*j+1],
                          fmaf(p[3*i  ], p[3*j  ], w)));
                float h = fmaxf(d, 0.0f);    // FMNMX (alu pipe)
                if ((k >> 1) & 1) a1 += h; else a0 += h;
            }
            k++;
        }
    }
    return a0 + a1;
}

__global__ __launch_bounds__(THREADS, 6)   // 85-reg cap; ~80 demand (R8-measured)
void sep_loss_fused(const float* __restrict__ kps, int B, int grid,
                    float invB, float* __restrict__ out) {
    __shared__ __align__(16) float s[TILE_ROWS * ROW_F];   // 13056 B
    __shared__ __align__(8)  unsigned long long mbar;
    __shared__ float wsum[THREADS / 32];
    __shared__ bool  isLast;

    const int tid = threadIdx.x;
    const int half = tid >> 6;               // 0 or 1, warp-uniform
    const int row  = tid & 63;               // local row 0..63
    const int rowBase = blockIdx.x * TILE_ROWS;
    const int rowsHere = min(TILE_ROWS, B - rowBase);
    const uint32_t mb = smem_u32(&mbar);

    if (rowsHere == TILE_ROWS) {
        if (tid == 0)
            asm volatile("mbarrier.init.shared.b64 [%0], 1;" :: "r"(mb) : "memory");
        __syncthreads();
        if (tid == 0) {
            asm volatile("mbarrier.arrive.expect_tx.shared.b64 _, [%0], %1;"
                         :: "r"(mb), "r"((uint32_t)TILE_BYTES) : "memory");
            asm volatile(
                "cp.async.bulk.shared::cta.global.mbarrier::complete_tx::bytes "
                "[%0], [%1], %2, [%3];"
                :: "r"(smem_u32(s)), "l"(kps + (size_t)rowBase * ROW_F),
                   "r"((uint32_t)TILE_BYTES), "r"(mb)
                : "memory");
        }
        mbar_wait0(mb);
    } else {
        const float* src = kps + (size_t)rowBase * ROW_F;
        for (int i = tid; i < rowsHere * ROW_F; i += THREADS) s[i] = src[i];
        __syncthreads();
    }

    float acc = 0.0f;
    if (row < rowsHere) {
        const float* __restrict__ rp = s + row * ROW_F;
        // warp-uniform branch: each warp runs exactly one specialization
        acc = half ? row_pairs_half<1>(rp) : row_pairs_half<0>(rp);
    }
    // hinge = 2*max(0,d); ordered pairs double again -> x4
    acc *= 4.0f;

    // ---- deterministic block reduction (4 warps) ----
    #pragma unroll
    for (int off = 16; off > 0; off >>= 1)
        acc += __shfl_down_sync(0xFFFFFFFFu, acc, off);
    if ((tid & 31) == 0) wsum[tid >> 5] = acc;
    __syncthreads();

    if (tid == 0) {
        g_partials[blockIdx.x] = (wsum[0] + wsum[1]) + (wsum[2] + wsum[3]);
        // release-inc orders the store; wraps to 0 at grid-1 (replay-safe)
        unsigned int c;
        asm volatile("atom.acq_rel.gpu.global.inc.u32 %0, [%1], %2;"
                     : "=r"(c)
                     : "l"(&g_done_count), "r"((unsigned int)(grid - 1))
                     : "memory");
        isLast = (c == (unsigned int)(grid - 1));
    }
    __syncthreads();

    // ---- last block: vectorized fixed-order final reduction ----
    if (isLast) {
        float v = 0.0f;
        const int nvec = grid >> 2;               // 512 for grid=2048
        const float4* gp = reinterpret_cast<const float4*>(g_partials);
        #pragma unroll 4
        for (int i = tid; i < nvec; i += THREADS) {
            float4 f = gp[i];
            v += (f.x + f.y) + (f.z + f.w);
        }
        for (int i = (nvec << 2) + tid; i < grid; i += THREADS)
            v += g_partials[i];
        #pragma unroll
        for (int off = 16; off > 0; off >>= 1)
            v += __shfl_down_sync(0xFFFFFFFFu, v, off);
        if ((tid & 31) == 0) wsum[tid >> 5] = v;
        __syncthreads();
        if (tid == 0)
            out[0] = ((wsum[0] + wsum[1]) + (wsum[2] + wsum[3])) * invB;
    }
}

extern "C" void kernel_launch(void* const* d_in, const int* in_sizes, int n_in,
                              void* d_out, int out_size) {
    const float* kps = (const float*)d_in[0];
    const int B = in_sizes[0] / ROW_F;
    const int grid = (B + TILE_ROWS - 1) / TILE_ROWS;   // 2048 for B=131072

    sep_loss_fused<<<grid, THREADS>>>(kps, B, grid, 1.0f / (float)B,
                                      (float*)d_out);
}